// round 5
// baseline (speedup 1.0000x reference)
#include <cuda_runtime.h>

// ODEFunc: 4 x { Y = X @ A^T (V-mix) ; Z = w @ Y + b (C-GEMM) ; X = relu(Z + X) }
// N=64, C=256, T=64, V=25.  One block per (n,t) position; whole recurrence in SMEM.

#define N_ 64
#define C_ 256
#define T_ 64
#define V_ 25
#define VP 28          // padded V (float4-aligned Y rows)
#define WSTR 34        // w tile row stride (even -> float2 aligned; /2=17 odd -> conflict-free 64b)
#define CHUNK 32       // c-columns of w staged per pass

// dynamic smem partition (floats)
#define XS_OFF 0
#define XS_LEN (C_ * V_)            // 6400
#define AS_OFF (XS_OFF + XS_LEN)
#define AS_LEN (V_ * VP)            // 700
#define WS_OFF (AS_OFF + AS_LEN)
#define WS_LEN (C_ * WSTR)          // 8704
#define YS_OFF (WS_OFF + WS_LEN)
#define YS_LEN (C_ * VP + 8)        // 7176 (8 pad floats so row-overrun reads stay in-bounds)
#define SMEM_FLOATS (YS_OFF + YS_LEN)
#define SMEM_BYTES  (SMEM_FLOATS * 4)

__global__ __launch_bounds__(256, 2)
void odefunc_kernel(const float* __restrict__ x,
                    const float* __restrict__ A,
                    const float* __restrict__ w1, const float* __restrict__ b1,
                    const float* __restrict__ w2, const float* __restrict__ b2,
                    const float* __restrict__ w3, const float* __restrict__ b3,
                    const float* __restrict__ w4, const float* __restrict__ b4,
                    float* __restrict__ out)
{
    extern __shared__ float smem[];
    float* Xs = smem + XS_OFF;   // [C][25]   stride 25 (odd -> conflict-free scalar)
    float* As = smem + AS_OFF;   // [25][VP]  zero-padded cols 25..27
    float* Ws = smem + WS_OFF;   // [C][WSTR] w chunk, float2-accessed
    float* Ys = smem + YS_OFF;   // [C][VP]   zero-padded cols 25..27

    const int tid = threadIdx.x;
    const int pos = blockIdx.x;          // 0..4095
    const int n = pos >> 6;
    const int t = pos & 63;
    const int base = (n * (C_ * T_) + t) * V_;   // element offset of (n, 0, t, 0); c stride = T_*V_

    // ---- load A (padded) ----
    for (int i = tid; i < V_ * VP; i += 256) {
        int v = i / VP, u = i - v * VP;
        As[i] = (u < V_) ? A[v * V_ + u] : 0.0f;
    }

    // ---- load X tile: thread = channel row ----
    {
        const float* xp = x + base + tid * (T_ * V_);
        #pragma unroll
        for (int v = 0; v < V_; v++) Xs[tid * V_ + v] = xp[v];
    }

    const float* wptr[4] = { w1, w2, w3, w4 };
    const float* bptr[4] = { b1, b2, b3, b4 };

    // stage-B thread mapping: og = output-channel base, vg = v-group
    const int og = tid & 63;
    const int vg = tid >> 6;
    const int v0 = vg * 8;               // v-groups: [0,8) [8,16) [16,24) [24,28)

    for (int layer = 0; layer < 4; layer++) {
        const float* __restrict__ w = wptr[layer];
        const float* __restrict__ b = bptr[layer];

        __syncthreads();   // X ready (initial load or previous epilogue)

        // ---------- stage A: Y[c][v] = sum_u X[c][u] * A[v][u]  (thread = c) ----------
        {
            float xr[VP];
            #pragma unroll
            for (int u = 0; u < V_; u++) xr[u] = Xs[tid * V_ + u];
            #pragma unroll
            for (int u = V_; u < VP; u++) xr[u] = 0.0f;

            #pragma unroll
            for (int v = 0; v < V_; v++) {
                float s = 0.0f;
                #pragma unroll
                for (int u4 = 0; u4 < VP; u4 += 4) {
                    float4 a4 = *reinterpret_cast<const float4*>(&As[v * VP + u4]);  // broadcast
                    s += xr[u4] * a4.x + xr[u4 + 1] * a4.y + xr[u4 + 2] * a4.z + xr[u4 + 3] * a4.w;
                }
                Ys[tid * VP + v] = s;
            }
            #pragma unroll
            for (int v = V_; v < VP; v++) Ys[tid * VP + v] = 0.0f;
        }

        // ---------- stage B: Z[o][v] = b[o] + sum_c w[o][c] * Y[c][v] ----------
        float acc[4][8];
        #pragma unroll
        for (int r = 0; r < 4; r++) {
            float bv = b[og + r * 64];
            #pragma unroll
            for (int j = 0; j < 8; j++) acc[r][j] = bv;
        }

        for (int c0 = 0; c0 < C_; c0 += CHUNK) {
            __syncthreads();   // previous chunk fully consumed
            // cooperative load: 256 rows x 32 cols = 2048 float4, 8 per thread (coalesced 128B)
            #pragma unroll
            for (int k = 0; k < 8; k++) {
                int i = tid + k * 256;          // 0..2047
                int o = i >> 3;
                int q = i & 7;
                float4 wv = *reinterpret_cast<const float4*>(&w[o * C_ + c0 + q * 4]);
                float2* dst = reinterpret_cast<float2*>(&Ws[o * WSTR + q * 4]);
                dst[0] = make_float2(wv.x, wv.y);
                dst[1] = make_float2(wv.z, wv.w);
            }
            __syncthreads();   // chunk visible

            #pragma unroll
            for (int cc = 0; cc < CHUNK; cc += 2) {
                // w: 4 conflict-free float2 loads (covers cc and cc+1)
                float2 wv0 = *reinterpret_cast<const float2*>(&Ws[(og      ) * WSTR + cc]);
                float2 wv1 = *reinterpret_cast<const float2*>(&Ws[(og +  64) * WSTR + cc]);
                float2 wv2 = *reinterpret_cast<const float2*>(&Ws[(og + 128) * WSTR + cc]);
                float2 wv3 = *reinterpret_cast<const float2*>(&Ws[(og + 192) * WSTR + cc]);
                const float* yrA = &Ys[(c0 + cc) * VP + v0];
                const float* yrB = yrA + VP;
                float4 ya0 = *reinterpret_cast<const float4*>(yrA);      // broadcast in-warp
                float4 yb0 = *reinterpret_cast<const float4*>(yrB);

                #pragma unroll
                for (int r = 0; r < 4; r++) {
                    float wa = (r == 0) ? wv0.x : (r == 1) ? wv1.x : (r == 2) ? wv2.x : wv3.x;
                    float wb = (r == 0) ? wv0.y : (r == 1) ? wv1.y : (r == 2) ? wv2.y : wv3.y;
                    acc[r][0] += wa * ya0.x;  acc[r][1] += wa * ya0.y;
                    acc[r][2] += wa * ya0.z;  acc[r][3] += wa * ya0.w;
                    acc[r][0] += wb * yb0.x;  acc[r][1] += wb * yb0.y;
                    acc[r][2] += wb * yb0.z;  acc[r][3] += wb * yb0.w;
                }
                if (vg != 3) {   // warp-uniform: groups 0-2 carry 8 v's
                    float4 ya1 = *reinterpret_cast<const float4*>(yrA + 4);
                    float4 yb1 = *reinterpret_cast<const float4*>(yrB + 4);
                    #pragma unroll
                    for (int r = 0; r < 4; r++) {
                        float wa = (r == 0) ? wv0.x : (r == 1) ? wv1.x : (r == 2) ? wv2.x : wv3.x;
                        float wb = (r == 0) ? wv0.y : (r == 1) ? wv1.y : (r == 2) ? wv2.y : wv3.y;
                        acc[r][4] += wa * ya1.x;  acc[r][5] += wa * ya1.y;
                        acc[r][6] += wa * ya1.z;  acc[r][7] += wa * ya1.w;
                        acc[r][4] += wb * yb1.x;  acc[r][5] += wb * yb1.y;
                        acc[r][6] += wb * yb1.z;  acc[r][7] += wb * yb1.w;
                    }
                }
            }
        }

        __syncthreads();   // all stage-B reads of Ys/Ws done before X is rewritten

        // ---------- epilogue: X = relu(Z + X), in place ----------
        const int nv = (vg == 3) ? 4 : 8;
        #pragma unroll
        for (int r = 0; r < 4; r++) {
            int o = og + r * 64;
            #pragma unroll 8
            for (int j = 0; j < 8; j++) {
                if (j < nv) {
                    int v = v0 + j;
                    if (v < V_) {
                        float val = acc[r][j] + Xs[o * V_ + v];
                        Xs[o * V_ + v] = fmaxf(val, 0.0f);
                    }
                }
            }
        }
    }

    __syncthreads();
    // ---- store result: thread = channel row ----
    {
        float* op = out + base + tid * (T_ * V_);
        #pragma unroll
        for (int v = 0; v < V_; v++) op[v] = Xs[tid * V_ + v];
    }
}

extern "C" void kernel_launch(void* const* d_in, const int* in_sizes, int n_in,
                              void* d_out, int out_size)
{
    // inputs (metadata order): t, x, A, w1, b1, w2, b2, w3, b3, w4, b4
    const float* x  = (const float*)d_in[1];
    const float* A  = (const float*)d_in[2];
    const float* w1 = (const float*)d_in[3];
    const float* b1 = (const float*)d_in[4];
    const float* w2 = (const float*)d_in[5];
    const float* b2 = (const float*)d_in[6];
    const float* w3 = (const float*)d_in[7];
    const float* b3 = (const float*)d_in[8];
    const float* w4 = (const float*)d_in[9];
    const float* b4 = (const float*)d_in[10];
    float* out = (float*)d_out;

    cudaFuncSetAttribute(odefunc_kernel,
                         cudaFuncAttributeMaxDynamicSharedMemorySize, SMEM_BYTES);

    odefunc_kernel<<<N_ * T_, 256, SMEM_BYTES>>>(
        x, A, w1, b1, w2, b2, w3, b3, w4, b4, out);
}

// round 6
// speedup vs baseline: 1.0022x; 1.0022x over previous
#include <cuda_runtime.h>

// ODEFunc: 4 x { Y = X @ A^T (V-mix) ; Z = w @ Y + b (C-GEMM) ; X = relu(Z + X) }
// N=64, C=256, T=64, V=25.  One block per (n,t) position; whole recurrence in SMEM.

#define N_ 64
#define C_ 256
#define T_ 64
#define V_ 25
#define VP 28          // padded V (float4-aligned Y rows)
#define WSTR 34        // w tile row stride (even -> float2 aligned; /2=17 odd -> conflict-free 64b)
#define CHUNK 32       // c-columns of w staged per pass

// dynamic smem partition (floats)
#define XS_OFF 0
#define XS_LEN (C_ * V_)            // 6400
#define AS_OFF (XS_OFF + XS_LEN)
#define AS_LEN (V_ * VP)            // 700
#define WS_OFF (AS_OFF + AS_LEN)
#define WS_LEN (C_ * WSTR)          // 8704
#define YS_OFF (WS_OFF + WS_LEN)
#define YS_LEN (C_ * VP + 8)        // 7176 (8 pad floats so row-overrun reads stay in-bounds)
#define SMEM_FLOATS (YS_OFF + YS_LEN)
#define SMEM_BYTES  (SMEM_FLOATS * 4)

__global__ __launch_bounds__(256, 2)
void odefunc_kernel(const float* __restrict__ x,
                    const float* __restrict__ A,
                    const float* __restrict__ w1, const float* __restrict__ b1,
                    const float* __restrict__ w2, const float* __restrict__ b2,
                    const float* __restrict__ w3, const float* __restrict__ b3,
                    const float* __restrict__ w4, const float* __restrict__ b4,
                    float* __restrict__ out)
{
    extern __shared__ float smem[];
    float* Xs = smem + XS_OFF;   // [C][25]   stride 25 (odd -> conflict-free scalar)
    float* As = smem + AS_OFF;   // [25][VP]  zero-padded cols 25..27
    float* Ws = smem + WS_OFF;   // [C][WSTR] w chunk, float2-accessed
    float* Ys = smem + YS_OFF;   // [C][VP]   zero-padded cols 25..27

    const int tid = threadIdx.x;
    const int pos = blockIdx.x;          // 0..4095
    const int n = pos >> 6;
    const int t = pos & 63;
    const int base = (n * (C_ * T_) + t) * V_;   // element offset of (n, 0, t, 0); c stride = T_*V_

    // ---- load A (padded) ----
    for (int i = tid; i < V_ * VP; i += 256) {
        int v = i / VP, u = i - v * VP;
        As[i] = (u < V_) ? A[v * V_ + u] : 0.0f;
    }

    // ---- load X tile: thread = channel row ----
    {
        const float* xp = x + base + tid * (T_ * V_);
        #pragma unroll
        for (int v = 0; v < V_; v++) Xs[tid * V_ + v] = xp[v];
    }

    const float* wptr[4] = { w1, w2, w3, w4 };
    const float* bptr[4] = { b1, b2, b3, b4 };

    // stage-B thread mapping: og = output-channel base, vg = v-group
    const int og = tid & 63;
    const int vg = tid >> 6;
    const int v0 = vg * 8;               // v-groups: [0,8) [8,16) [16,24) [24,28)

    for (int layer = 0; layer < 4; layer++) {
        const float* __restrict__ w = wptr[layer];
        const float* __restrict__ b = bptr[layer];

        __syncthreads();   // X ready (initial load or previous epilogue)

        // ---------- stage A: Y[c][v] = sum_u X[c][u] * A[v][u]  (thread = c) ----------
        {
            float xr[VP];
            #pragma unroll
            for (int u = 0; u < V_; u++) xr[u] = Xs[tid * V_ + u];
            #pragma unroll
            for (int u = V_; u < VP; u++) xr[u] = 0.0f;

            #pragma unroll
            for (int v = 0; v < V_; v++) {
                float s = 0.0f;
                #pragma unroll
                for (int u4 = 0; u4 < VP; u4 += 4) {
                    float4 a4 = *reinterpret_cast<const float4*>(&As[v * VP + u4]);  // broadcast
                    s += xr[u4] * a4.x + xr[u4 + 1] * a4.y + xr[u4 + 2] * a4.z + xr[u4 + 3] * a4.w;
                }
                Ys[tid * VP + v] = s;
            }
            #pragma unroll
            for (int v = V_; v < VP; v++) Ys[tid * VP + v] = 0.0f;
        }

        // ---------- stage B: Z[o][v] = b[o] + sum_c w[o][c] * Y[c][v] ----------
        float acc[4][8];
        #pragma unroll
        for (int r = 0; r < 4; r++) {
            float bv = b[og + r * 64];
            #pragma unroll
            for (int j = 0; j < 8; j++) acc[r][j] = bv;
        }

        for (int c0 = 0; c0 < C_; c0 += CHUNK) {
            __syncthreads();   // previous chunk fully consumed
            // cooperative load: 256 rows x 32 cols = 2048 float4, 8 per thread (coalesced 128B)
            #pragma unroll
            for (int k = 0; k < 8; k++) {
                int i = tid + k * 256;          // 0..2047
                int o = i >> 3;
                int q = i & 7;
                float4 wv = *reinterpret_cast<const float4*>(&w[o * C_ + c0 + q * 4]);
                float2* dst = reinterpret_cast<float2*>(&Ws[o * WSTR + q * 4]);
                dst[0] = make_float2(wv.x, wv.y);
                dst[1] = make_float2(wv.z, wv.w);
            }
            __syncthreads();   // chunk visible

            #pragma unroll
            for (int cc = 0; cc < CHUNK; cc += 2) {
                // w: 4 conflict-free float2 loads (covers cc and cc+1)
                float2 wv0 = *reinterpret_cast<const float2*>(&Ws[(og      ) * WSTR + cc]);
                float2 wv1 = *reinterpret_cast<const float2*>(&Ws[(og +  64) * WSTR + cc]);
                float2 wv2 = *reinterpret_cast<const float2*>(&Ws[(og + 128) * WSTR + cc]);
                float2 wv3 = *reinterpret_cast<const float2*>(&Ws[(og + 192) * WSTR + cc]);
                const float* yrA = &Ys[(c0 + cc) * VP + v0];
                const float* yrB = yrA + VP;
                float4 ya0 = *reinterpret_cast<const float4*>(yrA);      // broadcast in-warp
                float4 yb0 = *reinterpret_cast<const float4*>(yrB);

                #pragma unroll
                for (int r = 0; r < 4; r++) {
                    float wa = (r == 0) ? wv0.x : (r == 1) ? wv1.x : (r == 2) ? wv2.x : wv3.x;
                    float wb = (r == 0) ? wv0.y : (r == 1) ? wv1.y : (r == 2) ? wv2.y : wv3.y;
                    acc[r][0] += wa * ya0.x;  acc[r][1] += wa * ya0.y;
                    acc[r][2] += wa * ya0.z;  acc[r][3] += wa * ya0.w;
                    acc[r][0] += wb * yb0.x;  acc[r][1] += wb * yb0.y;
                    acc[r][2] += wb * yb0.z;  acc[r][3] += wb * yb0.w;
                }
                if (vg != 3) {   // warp-uniform: groups 0-2 carry 8 v's
                    float4 ya1 = *reinterpret_cast<const float4*>(yrA + 4);
                    float4 yb1 = *reinterpret_cast<const float4*>(yrB + 4);
                    #pragma unroll
                    for (int r = 0; r < 4; r++) {
                        float wa = (r == 0) ? wv0.x : (r == 1) ? wv1.x : (r == 2) ? wv2.x : wv3.x;
                        float wb = (r == 0) ? wv0.y : (r == 1) ? wv1.y : (r == 2) ? wv2.y : wv3.y;
                        acc[r][4] += wa * ya1.x;  acc[r][5] += wa * ya1.y;
                        acc[r][6] += wa * ya1.z;  acc[r][7] += wa * ya1.w;
                        acc[r][4] += wb * yb1.x;  acc[r][5] += wb * yb1.y;
                        acc[r][6] += wb * yb1.z;  acc[r][7] += wb * yb1.w;
                    }
                }
            }
        }

        __syncthreads();   // all stage-B reads of Ys/Ws done before X is rewritten

        // ---------- epilogue: X = relu(Z + X), in place ----------
        const int nv = (vg == 3) ? 4 : 8;
        #pragma unroll
        for (int r = 0; r < 4; r++) {
            int o = og + r * 64;
            #pragma unroll 8
            for (int j = 0; j < 8; j++) {
                if (j < nv) {
                    int v = v0 + j;
                    if (v < V_) {
                        float val = acc[r][j] + Xs[o * V_ + v];
                        Xs[o * V_ + v] = fmaxf(val, 0.0f);
                    }
                }
            }
        }
    }

    __syncthreads();
    // ---- store result: thread = channel row ----
    {
        float* op = out + base + tid * (T_ * V_);
        #pragma unroll
        for (int v = 0; v < V_; v++) op[v] = Xs[tid * V_ + v];
    }
}

extern "C" void kernel_launch(void* const* d_in, const int* in_sizes, int n_in,
                              void* d_out, int out_size)
{
    // inputs (metadata order): t, x, A, w1, b1, w2, b2, w3, b3, w4, b4
    const float* x  = (const float*)d_in[1];
    const float* A  = (const float*)d_in[2];
    const float* w1 = (const float*)d_in[3];
    const float* b1 = (const float*)d_in[4];
    const float* w2 = (const float*)d_in[5];
    const float* b2 = (const float*)d_in[6];
    const float* w3 = (const float*)d_in[7];
    const float* b3 = (const float*)d_in[8];
    const float* w4 = (const float*)d_in[9];
    const float* b4 = (const float*)d_in[10];
    float* out = (float*)d_out;

    cudaFuncSetAttribute(odefunc_kernel,
                         cudaFuncAttributeMaxDynamicSharedMemorySize, SMEM_BYTES);

    odefunc_kernel<<<N_ * T_, 256, SMEM_BYTES>>>(
        x, A, w1, b1, w2, b2, w3, b3, w4, b4, out);
}